// round 4
// baseline (speedup 1.0000x reference)
#include <cuda_runtime.h>
#include <cstdint>

#define BATCH 16384
typedef unsigned long long u64;

// ---------------- device scratch (static allocation only) ----------------
__device__ float g_pool1[BATCH * 396];   // pooled conv1 output [b][oc(6)][py(11)*6+px]
__device__ float g_wc1[456];             // conv1 w re-laid [ch][dy][dx][oc0..5]
__device__ float g_wc2[2400];            // conv2 w re-laid [ci][dy][dx][oc0..15]
__device__ float g_wc3[3072];            // conv3 w re-laid [ci*3+dy][oc0..63]
__device__ float g_lfc1T[2048];          // lfc1 transposed [i(64)][j(32)]
__device__ float g_fcwT[256];            // fc_w transposed [i(8)][j(32)]
__device__ float g_watt[1024];           // folded attention weight [j(32)][i(32)]
__device__ float g_batt[32];             // folded attention bias

__device__ __forceinline__ float relu(float x) { return x > 0.f ? x : 0.f; }
__device__ __forceinline__ u64 dup2(float x) {
    u64 r; asm("mov.b64 %0, {%1,%1};" : "=l"(r) : "f"(x)); return r;
}
__device__ __forceinline__ void fma2(u64& d, u64 a, u64 b) {
    asm("fma.rn.f32x2 %0, %1, %2, %0;" : "+l"(d) : "l"(a), "l"(b));
}
__device__ __forceinline__ float2 u2f(u64 v) {
    float2 r; asm("mov.b64 {%0,%1}, %2;" : "=f"(r.x), "=f"(r.y) : "l"(v)); return r;
}

// ---------------- L0: weight re-layout + attention folding ----------------
__global__ void k_prep(const float* __restrict__ w1, const float* __restrict__ w2,
                       const float* __restrict__ w3, const float* __restrict__ lfc1,
                       const float* __restrict__ fcw, const float* __restrict__ outw,
                       const float* __restrict__ ipw, const float* __restrict__ ipb,
                       const float* __restrict__ outb) {
    int tid = blockIdx.x * blockDim.x + threadIdx.x;
    int nt = gridDim.x * blockDim.x;
    for (int i = tid; i < 450; i += nt) {
        int oc = i % 6; int r = i / 6; int dx = r % 5; r /= 5; int dy = r % 5; int ch = r / 5;
        g_wc1[i] = w1[((oc * 3 + ch) * 5 + dy) * 5 + dx];
    }
    for (int i = tid; i < 2400; i += nt) {
        int oc = i % 16; int r = i / 16; int dx = r % 5; r /= 5; int dy = r % 5; int ci = r / 5;
        g_wc2[i] = w2[((oc * 6 + ci) * 5 + dy) * 5 + dx];
    }
    for (int i = tid; i < 3072; i += nt) {
        int o = i % 64; int r = i / 64; int dy = r % 3; int ci = r / 3;
        g_wc3[i] = w3[(o * 16 + ci) * 3 + dy];
    }
    for (int i = tid; i < 2048; i += nt) {
        int j = i % 32; int k = i / 32; g_lfc1T[i] = lfc1[j * 64 + k];
    }
    for (int i = tid; i < 256; i += nt) {
        int j = i % 32; int k = i / 32; g_fcwT[i] = fcw[j * 8 + k];
    }
    // W_att[i][j] = sum_k out_w[i,k] * vw[k,j], stored as g_watt[j*32+i]
    for (int i = tid; i < 1024; i += nt) {
        int ii = i % 32; int j = i / 32;
        float s = 0.f;
        for (int k = 0; k < 32; k++) s += outw[ii * 32 + k] * ipw[(64 + k) * 32 + j];
        g_watt[i] = s;
    }
    for (int i = tid; i < 32; i += nt) {
        float s = outb[i];
        for (int k = 0; k < 32; k++) s += outw[i * 32 + k] * ipb[64 + k];
        g_batt[i] = s;
    }
}

// ---------------- L1: board build + conv1 + relu + avgpool (fused) ----------------
// 128 threads = 2 samples x 64 threads. Board in shared with 2-halo (26x16 per ch, zeroed).
__global__ __launch_bounds__(128) void k_board_conv1(
    const int* __restrict__ t, const int* __restrict__ ptab,
    const float* __restrict__ b1, float* __restrict__ boardOut, int writeBoard) {
    __shared__ __align__(16) float sb[2][3 * 416];   // [26 rows][16 cols] per channel
    __shared__ __align__(8) float wc1s[456];
    __shared__ float b1s[8];

    int tid = threadIdx.x;
    int g = tid >> 6;
    int lt = tid & 63;
    int b = blockIdx.x * 2 + g;
    float* S = sb[g];

    float4 z4 = make_float4(0.f, 0.f, 0.f, 0.f);
    for (int i = lt; i < 1248 / 4; i += 64) ((float4*)S)[i] = z4;
    for (int i = tid; i < 450; i += 128) wc1s[i] = g_wc1[i];
    if (tid < 6) b1s[tid] = b1[tid];
    __syncthreads();

    const int* trow = t + (size_t)b * 232;
    // channel 0 interior: board[r][c] at padded (r, c+1) -> shared (r+2, c+3)
    for (int i = lt; i < 210; i += 64) {
        int r = i / 10, c = i % 10;
        S[(r + 2) * 16 + (c + 3)] = (float)trow[22 + i];
    }
    // padding frame = 1.0 on all 3 channels: padded cols 0,11 rows 0..21 and row 21 all cols
    for (int i = lt; i < 168; i += 64) {
        int ch = i / 56, j = i % 56;
        int r, c;
        if (j < 22) { r = j; c = 0; }
        else if (j < 44) { r = j - 22; c = 11; }
        else { r = 21; c = j - 44; }
        S[ch * 416 + (r + 2) * 16 + (c + 2)] = 1.0f;
    }
    // piece cells (channels 1 and 2)
    if (lt == 0) {
        int t1 = trow[1], t2 = trow[2], t3 = trow[3], t4 = trow[4], t8 = trow[8];
        const int* p = ptab + t8 * 64 + t4 * 16;
        int sel[4]; int cnt = 0;
        for (int i = 0; i < 16 && cnt < 4; i++) if (p[i] != 0) sel[cnt++] = i;
        for (int i = 0; i < 16 && cnt < 4; i++) if (p[i] == 0) sel[cnt++] = i;
        for (int s = 0; s < 4; s++) {
            int cy = sel[s] >> 2, cx = sel[s] & 3;
            int x = cx + t1 - 2;
            int y = cy + t2;
            int ny = y + t3;
            if (y >= 0 && ny >= 0 && x >= 0 && x < 10) {
                if (y < 21)  S[1 * 416 + (y + 2) * 16 + (x + 3)] = 1.0f;
                if (ny < 21) S[2 * 416 + (ny + 2) * 16 + (x + 3)] = 1.0f;
            }
        }
    }
    __syncthreads();

    // write padded board (B,3,22,12) to output
    if (writeBoard) {
        float* ob = boardOut + (size_t)b * 792;
        for (int i = lt; i < 792; i += 64) {
            int ch = i / 264, rem = i % 264;
            int r = rem / 12, c = rem % 12;
            ob[i] = S[ch * 416 + (r + 2) * 16 + (c + 2)];
        }
    }

    // conv1 + relu + avgpool, one pooled position per thread (66 positions)
    for (int pp = lt; pp < 66; pp += 64) {
        int py = pp / 6, px = pp % 6;
        u64 acc00[3] = {0, 0, 0}, acc01[3] = {0, 0, 0};
        u64 acc10[3] = {0, 0, 0}, acc11[3] = {0, 0, 0};
        for (int ch = 0; ch < 3; ch++) {
            const float* plane = S + ch * 416;
            #pragma unroll
            for (int dy = 0; dy < 5; dy++) {
                const u64* r0 = (const u64*)(plane + (2 * py + dy) * 16 + 2 * px);
                const u64* r1 = (const u64*)(plane + (2 * py + dy + 1) * 16 + 2 * px);
                float2 u0 = u2f(r0[0]), u1 = u2f(r0[1]), u2v = u2f(r0[2]);
                float2 v0 = u2f(r1[0]), v1 = u2f(r1[1]), v2v = u2f(r1[2]);
                float ra[6] = {u0.x, u0.y, u1.x, u1.y, u2v.x, u2v.y};
                float rb[6] = {v0.x, v0.y, v1.x, v1.y, v2v.x, v2v.y};
                const u64* wp = (const u64*)(wc1s + (ch * 5 + dy) * 30);
                #pragma unroll
                for (int dx = 0; dx < 5; dx++) {
                    u64 w0 = wp[dx * 3 + 0], w1 = wp[dx * 3 + 1], w2w = wp[dx * 3 + 2];
                    u64 d00 = dup2(ra[dx]), d01 = dup2(ra[dx + 1]);
                    u64 d10 = dup2(rb[dx]), d11 = dup2(rb[dx + 1]);
                    fma2(acc00[0], w0, d00); fma2(acc00[1], w1, d00); fma2(acc00[2], w2w, d00);
                    fma2(acc01[0], w0, d01); fma2(acc01[1], w1, d01); fma2(acc01[2], w2w, d01);
                    fma2(acc10[0], w0, d10); fma2(acc10[1], w1, d10); fma2(acc10[2], w2w, d10);
                    fma2(acc11[0], w0, d11); fma2(acc11[1], w1, d11); fma2(acc11[2], w2w, d11);
                }
            }
        }
        float* dst = g_pool1 + (size_t)b * 396;
        #pragma unroll
        for (int k = 0; k < 3; k++) {
            float2 a00 = u2f(acc00[k]), a01 = u2f(acc01[k]);
            float2 a10 = u2f(acc10[k]), a11 = u2f(acc11[k]);
            float bb0 = b1s[2 * k], bb1 = b1s[2 * k + 1];
            float p0 = 0.25f * (relu(a00.x + bb0) + relu(a01.x + bb0) +
                                relu(a10.x + bb0) + relu(a11.x + bb0));
            float p1v = 0.25f * (relu(a00.y + bb1) + relu(a01.y + bb1) +
                                 relu(a10.y + bb1) + relu(a11.y + bb1));
            dst[(2 * k) * 66 + pp] = p0;
            dst[(2 * k + 1) * 66 + pp] = p1v;
        }
    }
}

// ---------------- L2: conv2 + pool + conv3 + fc + folded-attention + xf ----------------
// 256 threads = 8 warps, one sample per warp. Dynamic shared: weights + per-warp buffers.
__global__ __launch_bounds__(256) void k_tail(
    const int* __restrict__ t, const float* __restrict__ c2b,
    const float* __restrict__ c3b, const float* __restrict__ l1b,
    const float* __restrict__ fcb, float* __restrict__ out) {
    extern __shared__ float dsm[];
    float* w2s = dsm;                 // 2400
    float* w3s = w2s + 2400;          // 3072
    float* l1s = w3s + 3072;          // 2048
    float* was = l1s + 2048;          // 1024
    float* fws = was + 1024;          // 256
    float* bias = fws + 256;          // 176: [0:16)c2b [16:80)c3b [80:112)l1b [112:144)fcb [144:176)batt
    float* wbuf = bias + 176;         // 8 * 736

    int tid = threadIdx.x;
    for (int i = tid; i < 2400; i += 256) w2s[i] = g_wc2[i];
    for (int i = tid; i < 3072; i += 256) w3s[i] = g_wc3[i];
    for (int i = tid; i < 2048; i += 256) l1s[i] = g_lfc1T[i];
    for (int i = tid; i < 1024; i += 256) was[i] = g_watt[i];
    for (int i = tid; i < 256; i += 256) fws[i] = g_fcwT[i];
    for (int i = tid; i < 16; i += 256) bias[i] = c2b[i];
    for (int i = tid; i < 64; i += 256) bias[16 + i] = c3b[i];
    for (int i = tid; i < 32; i += 256) {
        bias[80 + i] = l1b[i];
        bias[112 + i] = fcb[i];
        bias[144 + i] = g_batt[i];
    }
    __syncthreads();

    int w = tid >> 5;
    int lane = tid & 31;
    int b = blockIdx.x * 8 + w;

    float* p1s = wbuf + w * 736;   // 400 (396 used)
    float* c2s = p1s + 400;        // 192 [oc][y(6)][x(2)]
    float* p2s = c2s + 192;        // 48  [ci][py(3)]
    float* x64s = p2s + 48;        // 64
    float* b2s = x64s + 64;        // 32

    for (int i = lane; i < 396; i += 32) p1s[i] = g_pool1[(size_t)b * 396 + i];
    __syncwarp();

    // conv2: lane -> oc = lane&15, x = lane>>4; computes rows y=0..5 (row 6 dropped by pool)
    {
        int oc = lane & 15;
        int xx = lane >> 4;
        float acc[6];
        float bb = bias[oc];
        #pragma unroll
        for (int y = 0; y < 6; y++) acc[y] = bb;
        for (int ci = 0; ci < 6; ci++) {
            #pragma unroll
            for (int dx = 0; dx < 5; dx++) {
                int col = xx + dx;
                const float* pc = p1s + ci * 66 + col;
                float c[10];
                #pragma unroll
                for (int j = 0; j < 10; j++) c[j] = pc[j * 6];
                const float* wb = w2s + ((ci * 5) * 5 + dx) * 16 + oc;
                #pragma unroll
                for (int dy = 0; dy < 5; dy++) {
                    float wv = wb[dy * 80];
                    acc[0] += wv * c[dy + 0];
                    acc[1] += wv * c[dy + 1];
                    acc[2] += wv * c[dy + 2];
                    acc[3] += wv * c[dy + 3];
                    acc[4] += wv * c[dy + 4];
                    acc[5] += wv * c[dy + 5];
                }
            }
        }
        #pragma unroll
        for (int y = 0; y < 6; y++) c2s[oc * 12 + y * 2 + xx] = relu(acc[y]);
    }
    __syncwarp();

    // pool2: 48 entries [oc][py]
    for (int i = lane; i < 48; i += 32) {
        int base = (i / 3) * 12 + (i % 3) * 4;
        p2s[i] = 0.25f * (c2s[base] + c2s[base + 1] + c2s[base + 2] + c2s[base + 3]);
    }
    __syncwarp();

    // conv3 + relu: 64 outputs, 2 per lane
    {
        float accA = bias[16 + lane];
        float accB = bias[16 + lane + 32];
        #pragma unroll
        for (int k = 0; k < 48; k++) {
            float iv = p2s[k];
            accA += iv * w3s[k * 64 + lane];
            accB += iv * w3s[k * 64 + lane + 32];
        }
        x64s[lane] = relu(accA);
        x64s[lane + 32] = relu(accB);
    }
    __syncwarp();

    // b2 = relu(lfc1(x64))
    {
        float acc = bias[80 + lane];
        #pragma unroll
        for (int i = 0; i < 64; i++) acc += x64s[i] * l1s[i * 32 + lane];
        float v = relu(acc);
        b2s[lane] = v;
        out[(size_t)b * 96 + 64 + lane] = v;
    }
    __syncwarp();

    // a = W_att @ b2 + b_att (folded attention — softmax over single key is exactly 1)
    {
        float acc = bias[144 + lane];
        #pragma unroll
        for (int k = 0; k < 32; k++) acc += b2s[k] * was[k * 32 + lane];
        out[(size_t)b * 96 + 32 + lane] = acc;
    }

    // xf = relu(t[:, :8] @ fc_w.T + fc_b)
    {
        const int* trow = t + (size_t)b * 232;
        float tv = (lane < 8) ? (float)trow[lane] : 0.f;
        float acc = bias[112 + lane];
        #pragma unroll
        for (int i = 0; i < 8; i++) {
            float ti = __shfl_sync(0xffffffffu, tv, i);
            acc += ti * fws[i * 32 + lane];
        }
        out[(size_t)b * 96 + lane] = relu(acc);
    }
}

// ---------------- launch ----------------
extern "C" void kernel_launch(void* const* d_in, const int* in_sizes, int n_in,
                              void* d_out, int out_size) {
    const int* t = (const int*)d_in[0];
    const int* ptab = (const int*)d_in[1];
    const float* w1 = (const float*)d_in[2];
    const float* b1 = (const float*)d_in[3];
    const float* w2 = (const float*)d_in[4];
    const float* b2 = (const float*)d_in[5];
    const float* w3 = (const float*)d_in[6];
    const float* b3 = (const float*)d_in[7];
    const float* lfc1 = (const float*)d_in[8];
    const float* l1b = (const float*)d_in[9];
    const float* fcw = (const float*)d_in[10];
    const float* fcb = (const float*)d_in[11];
    const float* ipw = (const float*)d_in[13];
    const float* ipb = (const float*)d_in[14];
    const float* outw = (const float*)d_in[15];
    const float* outb = (const float*)d_in[16];
    float* out = (float*)d_out;

    // output layout: out.ravel() (B*96) then board.ravel() (B*792)
    int hasBoard = (out_size >= BATCH * (96 + 792)) ? 1 : 0;
    float* boardOut = out + (size_t)BATCH * 96;

    k_prep<<<8, 256>>>(w1, w2, w3, lfc1, fcw, outw, ipw, ipb, outb);
    k_board_conv1<<<BATCH / 2, 128>>>(t, ptab, b1, boardOut, hasBoard);

    static const int kTailSmem = (2400 + 3072 + 2048 + 1024 + 256 + 176 + 8 * 736) * 4;
    cudaFuncSetAttribute(k_tail, cudaFuncAttributeMaxDynamicSharedMemorySize, kTailSmem);
    k_tail<<<BATCH / 8, 256, kTailSmem>>>(t, b2, b3, l1b, fcb, out);
}